// round 2
// baseline (speedup 1.0000x reference)
#include <cuda_runtime.h>

// Problem constants
#define BATCH 8
#define CDIM  512
#define NPIX  1024   // 32*32
#define NHEAD 8
#define HDIM  64

// ---------------------------------------------------------------------------
// Device-global scratch (no allocations allowed in kernel_launch).
// Q/K/V/attn-out, each [B, C, N] fp32 = 16 MB -> 64 MB total.
// ---------------------------------------------------------------------------
__device__ float g_Q[BATCH * CDIM * NPIX];
__device__ float g_K[BATCH * CDIM * NPIX];
__device__ float g_V[BATCH * CDIM * NPIX];
__device__ float g_A[BATCH * CDIM * NPIX];

// ---------------------------------------------------------------------------
// 1x1-conv GEMM body: out[o,n] = sum_c W[o,c] * X[c,n] + bias[o] (+ resid)
// Block tile 128(o) x 128(n), BK=8, 256 threads, 8x8 register microtile.
// Double-buffered smem + register prefetch: ONE __syncthreads per k-step,
// global loads for step k+1 issued before the compute of step k.
// ---------------------------------------------------------------------------
__device__ __forceinline__ void gemm_body(
    const float* __restrict__ Xb,    // [C, N] for this batch
    const float* __restrict__ W,     // [C_out, C_in] row-major
    const float* __restrict__ bias,  // [C_out]
    float* __restrict__ outb,        // [C, N]
    const float* __restrict__ residb,// [C, N] or nullptr
    int obase, int nbase)
{
    __shared__ float Ws[2][8][128];   // Ws[buf][c][o]
    __shared__ float Xs[2][8][128];   // Xs[buf][c][n]

    const int tid = threadIdx.x;
    const int tx = tid & 15;       // n-tile coord
    const int ty = tid >> 4;       // o-tile coord

    float acc[8][8];
#pragma unroll
    for (int i = 0; i < 8; i++)
#pragma unroll
        for (int j = 0; j < 8; j++) acc[i][j] = 0.0f;

    // loader mapping
    const int wo = tid >> 1;            // 0..127
    const int wc = (tid & 1) * 4;       // 0 or 4
    const int xc = tid >> 5;            // 0..7
    const int xn = (tid & 31) * 4;      // 0..124

    const float* wp = W + (obase + wo) * CDIM + wc;
    const float* xp = Xb + xc * NPIX + nbase + xn;

    // Preload k-step 0 into buffer 0
    float4 wv = *(const float4*)(wp);
    float4 xv = *(const float4*)(xp);
    Ws[0][wc + 0][wo] = wv.x;
    Ws[0][wc + 1][wo] = wv.y;
    Ws[0][wc + 2][wo] = wv.z;
    Ws[0][wc + 3][wo] = wv.w;
    *(float4*)&Xs[0][xc][xn] = xv;
    __syncthreads();

    int buf = 0;
    for (int c0 = 8; c0 <= CDIM; c0 += 8) {
        // Issue next-step global loads first (latency hidden by compute below)
        const bool more = (c0 < CDIM);
        float4 wn, xn4;
        if (more) {
            wn  = *(const float4*)(wp + c0);
            xn4 = *(const float4*)(xp + (size_t)c0 * NPIX);
        }

        // Compute on current buffer
#pragma unroll
        for (int c = 0; c < 8; c++) {
            float a[8], bb[8];
            *(float4*)&a[0]  = *(const float4*)&Ws[buf][c][ty * 8];
            *(float4*)&a[4]  = *(const float4*)&Ws[buf][c][ty * 8 + 4];
            *(float4*)&bb[0] = *(const float4*)&Xs[buf][c][tx * 8];
            *(float4*)&bb[4] = *(const float4*)&Xs[buf][c][tx * 8 + 4];
#pragma unroll
            for (int i = 0; i < 8; i++)
#pragma unroll
                for (int j = 0; j < 8; j++)
                    acc[i][j] += a[i] * bb[j];
        }

        // Publish next buffer (safe: prior-step readers of it finished before
        // the barrier at the end of the previous iteration)
        if (more) {
            const int nb = buf ^ 1;
            Ws[nb][wc + 0][wo] = wn.x;
            Ws[nb][wc + 1][wo] = wn.y;
            Ws[nb][wc + 2][wo] = wn.z;
            Ws[nb][wc + 3][wo] = wn.w;
            *(float4*)&Xs[nb][xc][xn] = xn4;
            __syncthreads();
            buf = nb;
        }
    }

    // epilogue
#pragma unroll
    for (int i = 0; i < 8; i++) {
        const int orow = obase + ty * 8 + i;
        const float bv = bias[orow];
        float* op = outb + (size_t)orow * NPIX + nbase + tx * 8;
        if (residb != nullptr) {
            const float* rp = residb + (size_t)orow * NPIX + nbase + tx * 8;
#pragma unroll
            for (int j = 0; j < 8; j += 4) {
                float4 r = *(const float4*)(rp + j);
                float4 v;
                v.x = acc[i][j + 0] + bv + r.x;
                v.y = acc[i][j + 1] + bv + r.y;
                v.z = acc[i][j + 2] + bv + r.z;
                v.w = acc[i][j + 3] + bv + r.w;
                *(float4*)(op + j) = v;
            }
        } else {
#pragma unroll
            for (int j = 0; j < 8; j += 4) {
                float4 v;
                v.x = acc[i][j + 0] + bv;
                v.y = acc[i][j + 1] + bv;
                v.z = acc[i][j + 2] + bv;
                v.w = acc[i][j + 3] + bv;
                *(float4*)(op + j) = v;
            }
        }
    }
}

// ---------------------------------------------------------------------------
// QKV projection: grid (N/128, C/128, 3*B). z selects {Q,K,V} x batch.
// ---------------------------------------------------------------------------
__global__ void __launch_bounds__(256) qkv_kernel(
    const float* __restrict__ x,
    const float* __restrict__ Wq, const float* __restrict__ bq,
    const float* __restrict__ Wk, const float* __restrict__ bk,
    const float* __restrict__ Wv, const float* __restrict__ bv)
{
    const int z = blockIdx.z;
    const int mat = z >> 3;   // 0:Q 1:K 2:V
    const int b = z & 7;
    const float* W;
    const float* bias;
    float* out;
    if (mat == 0)      { W = Wq; bias = bq; out = g_Q; }
    else if (mat == 1) { W = Wk; bias = bk; out = g_K; }
    else               { W = Wv; bias = bv; out = g_V; }
    const size_t boff = (size_t)b * CDIM * NPIX;
    gemm_body(x + boff, W, bias, out + boff, nullptr,
              blockIdx.y * 128, blockIdx.x * 128);
}

// ---------------------------------------------------------------------------
// Output projection + residual: grid (N/128, C/128, B)
// ---------------------------------------------------------------------------
__global__ void __launch_bounds__(256) oproj_kernel(
    const float* __restrict__ x,
    const float* __restrict__ Wo, const float* __restrict__ bo,
    float* __restrict__ out)
{
    const int b = blockIdx.z;
    const size_t boff = (size_t)b * CDIM * NPIX;
    gemm_body(g_A + boff, Wo, bo, out + boff, x + boff,
              blockIdx.y * 128, blockIdx.x * 128);
}

// ---------------------------------------------------------------------------
// Flash-style attention, one block per (b, h, 64-row i-tile).
// Q/K/V are [hd=64, N=1024] slices (d-major, i/j contiguous).
//   S[i,j] = sum_d Q[d,i]*K[d,j] * (1/8);  P = online-softmax(S) over j
//   O[d,i] = sum_j V[d,j] * P[i,j]
// Thread map (16x16): S-phase: i = ty*4+ii, j = tx*4+jj  (softmax rows on ty,
// shuffle-reduce over the 16 tx lanes of a half-warp).
// O-phase: i = ty*4+ii, d = tx*4+dd (local softmax stats -> no smem broadcast).
// Smem: Qs[d][i] 16KB | Ks[d][j] overwritten by Ps[i][j] 16KB | Vt[j][d^] 16KB
// (XOR-swizzled so the j-loop float4 reads are conflict-free). Exactly 48KB.
// ---------------------------------------------------------------------------
#define VCOL(d, j) ((d) ^ ((j) & 0x3C))

__global__ void __launch_bounds__(256) attn_kernel()
{
    __shared__ float Qs[64 * 64];    // [d][i]
    __shared__ float KsPs[64 * 64];  // [d][j] then [i][j]
    __shared__ float Vt[64 * 64];    // [j][swizzled d]

    const int tid = threadIdx.x;
    const int tx = tid & 15;
    const int ty = tid >> 4;

    const int bh = blockIdx.y;
    const int b = bh >> 3;
    const int h = bh & 7;
    const int i0 = blockIdx.x * 64;

    const size_t base = ((size_t)b * CDIM + h * HDIM) * NPIX;
    const float* Qp = g_Q + base;
    const float* Kp = g_K + base;
    const float* Vp = g_V + base;
    float* Ap = g_A + base;

    // Load Q tile, pre-scaled by 1/sqrt(hd) = 0.125
    for (int t = tid; t < 1024; t += 256) {
        const int d = t >> 4;
        const int i4 = (t & 15) * 4;
        float4 q = *(const float4*)&Qp[(size_t)d * NPIX + i0 + i4];
        q.x *= 0.125f; q.y *= 0.125f; q.z *= 0.125f; q.w *= 0.125f;
        *(float4*)&Qs[d * 64 + i4] = q;
    }

    float rm[4], rl[4], o[4][4];
#pragma unroll
    for (int ii = 0; ii < 4; ii++) {
        rm[ii] = -1e30f;
        rl[ii] = 0.0f;
#pragma unroll
        for (int dd = 0; dd < 4; dd++) o[ii][dd] = 0.0f;
    }

    for (int j0 = 0; j0 < NPIX; j0 += 64) {
        __syncthreads();  // previous O-phase readers done (also fences Q load)

        // Load K tile ([d][j]) and V tile (transposed + swizzled [j][d])
        for (int t = tid; t < 1024; t += 256) {
            const int d = t >> 4;
            const int j4 = (t & 15) * 4;
            float4 kv = *(const float4*)&Kp[(size_t)d * NPIX + j0 + j4];
            *(float4*)&KsPs[d * 64 + j4] = kv;
            float4 vv = *(const float4*)&Vp[(size_t)d * NPIX + j0 + j4];
            Vt[(j4 + 0) * 64 + VCOL(d, j4 + 0)] = vv.x;
            Vt[(j4 + 1) * 64 + VCOL(d, j4 + 1)] = vv.y;
            Vt[(j4 + 2) * 64 + VCOL(d, j4 + 2)] = vv.z;
            Vt[(j4 + 3) * 64 + VCOL(d, j4 + 3)] = vv.w;
        }
        __syncthreads();

        // S = Q^T K (already scaled)
        float s[4][4];
#pragma unroll
        for (int ii = 0; ii < 4; ii++)
#pragma unroll
            for (int jj = 0; jj < 4; jj++) s[ii][jj] = 0.0f;

#pragma unroll 8
        for (int d = 0; d < 64; d++) {
            const float4 q = *(const float4*)&Qs[d * 64 + ty * 4];
            const float4 k = *(const float4*)&KsPs[d * 64 + tx * 4];
            s[0][0] += q.x * k.x; s[0][1] += q.x * k.y; s[0][2] += q.x * k.z; s[0][3] += q.x * k.w;
            s[1][0] += q.y * k.x; s[1][1] += q.y * k.y; s[1][2] += q.y * k.z; s[1][3] += q.y * k.w;
            s[2][0] += q.z * k.x; s[2][1] += q.z * k.y; s[2][2] += q.z * k.z; s[2][3] += q.z * k.w;
            s[3][0] += q.w * k.x; s[3][1] += q.w * k.y; s[3][2] += q.w * k.z; s[3][3] += q.w * k.w;
        }

        // Online softmax: rows i live in the 16 tx-lanes of a half-warp.
        float cval[4];
#pragma unroll
        for (int ii = 0; ii < 4; ii++) {
            float tm = fmaxf(fmaxf(s[ii][0], s[ii][1]), fmaxf(s[ii][2], s[ii][3]));
            tm = fmaxf(tm, __shfl_xor_sync(0xFFFFFFFFu, tm, 1));
            tm = fmaxf(tm, __shfl_xor_sync(0xFFFFFFFFu, tm, 2));
            tm = fmaxf(tm, __shfl_xor_sync(0xFFFFFFFFu, tm, 4));
            tm = fmaxf(tm, __shfl_xor_sync(0xFFFFFFFFu, tm, 8));
            const float mn = fmaxf(rm[ii], tm);
            const float cc = __expf(rm[ii] - mn);
            rm[ii] = mn;
            float ts = 0.0f;
#pragma unroll
            for (int jj = 0; jj < 4; jj++) {
                s[ii][jj] = __expf(s[ii][jj] - mn);
                ts += s[ii][jj];
            }
            ts += __shfl_xor_sync(0xFFFFFFFFu, ts, 1);
            ts += __shfl_xor_sync(0xFFFFFFFFu, ts, 2);
            ts += __shfl_xor_sync(0xFFFFFFFFu, ts, 4);
            ts += __shfl_xor_sync(0xFFFFFFFFu, ts, 8);
            rl[ii] = rl[ii] * cc + ts;
            cval[ii] = cc;
        }

        __syncthreads();  // all S-phase reads of Ks done before P overwrite

        // Write P[i][j] into the K-tile buffer (float4 along j).
#pragma unroll
        for (int ii = 0; ii < 4; ii++) {
            float4 p;
            p.x = s[ii][0]; p.y = s[ii][1]; p.z = s[ii][2]; p.w = s[ii][3];
            *(float4*)&KsPs[(ty * 4 + ii) * 64 + tx * 4] = p;
        }
        __syncthreads();

        // Rescale accumulators, then O += P * V^T
#pragma unroll
        for (int ii = 0; ii < 4; ii++) {
            const float cc = cval[ii];
#pragma unroll
            for (int dd = 0; dd < 4; dd++) o[ii][dd] *= cc;
        }

#pragma unroll 4
        for (int j = 0; j < 64; j++) {
            const float4 v = *(const float4*)&Vt[j * 64 + ((tx * 4) ^ (j & 0x3C))];
            const float p0 = KsPs[(ty * 4 + 0) * 64 + j];
            const float p1 = KsPs[(ty * 4 + 1) * 64 + j];
            const float p2 = KsPs[(ty * 4 + 2) * 64 + j];
            const float p3 = KsPs[(ty * 4 + 3) * 64 + j];
            o[0][0] += p0 * v.x; o[0][1] += p0 * v.y; o[0][2] += p0 * v.z; o[0][3] += p0 * v.w;
            o[1][0] += p1 * v.x; o[1][1] += p1 * v.y; o[1][2] += p1 * v.z; o[1][3] += p1 * v.w;
            o[2][0] += p2 * v.x; o[2][1] += p2 * v.y; o[2][2] += p2 * v.z; o[2][3] += p2 * v.w;
            o[3][0] += p3 * v.x; o[3][1] += p3 * v.y; o[3][2] += p3 * v.z; o[3][3] += p3 * v.w;
        }
    }

    // Normalize and stage O[d][i] in Qs (reuse), then coalesced global store.
    __syncthreads();
#pragma unroll
    for (int ii = 0; ii < 4; ii++) {
        const float inv = 1.0f / rl[ii];
#pragma unroll
        for (int dd = 0; dd < 4; dd++)
            Qs[(tx * 4 + dd) * 64 + ty * 4 + ii] = o[ii][dd] * inv;
    }
    __syncthreads();
    for (int t = tid; t < 1024; t += 256) {
        const int d = t >> 4;
        const int i4 = (t & 15) * 4;
        *(float4*)&Ap[(size_t)d * NPIX + i0 + i4] = *(const float4*)&Qs[d * 64 + i4];
    }
}

// ---------------------------------------------------------------------------
// Launch: QKV proj -> attention -> output proj (+residual). Default stream,
// no allocs, no syncs -> graph-capturable.
// ---------------------------------------------------------------------------
extern "C" void kernel_launch(void* const* d_in, const int* in_sizes, int n_in,
                              void* d_out, int out_size)
{
    const float* x  = (const float*)d_in[0];
    const float* Wq = (const float*)d_in[1];
    const float* bq = (const float*)d_in[2];
    const float* Wk = (const float*)d_in[3];
    const float* bk = (const float*)d_in[4];
    const float* Wv = (const float*)d_in[5];
    const float* bv = (const float*)d_in[6];
    const float* Wo = (const float*)d_in[7];
    const float* bo = (const float*)d_in[8];
    float* out = (float*)d_out;

    qkv_kernel<<<dim3(NPIX / 128, CDIM / 128, 3 * BATCH), 256>>>(
        x, Wq, bq, Wk, bk, Wv, bv);
    attn_kernel<<<dim3(NPIX / 64, BATCH * NHEAD), 256>>>();
    oproj_kernel<<<dim3(NPIX / 128, CDIM / 128, BATCH), 256>>>(x, Wo, bo, out);
}

// round 3
// speedup vs baseline: 1.0877x; 1.0877x over previous
#include <cuda_runtime.h>

// Problem constants
#define BATCH 8
#define CDIM  512
#define NPIX  1024   // 32*32
#define NHEAD 8
#define HDIM  64

// ---------------------------------------------------------------------------
// Device-global scratch (no allocations allowed in kernel_launch).
// ---------------------------------------------------------------------------
__device__ float g_Q[BATCH * CDIM * NPIX];
__device__ float g_K[BATCH * CDIM * NPIX];
__device__ float g_V[BATCH * CDIM * NPIX];
__device__ float g_A[BATCH * CDIM * NPIX];

// ---------------------------------------------------------------------------
// TF32 helpers
// ---------------------------------------------------------------------------
__device__ __forceinline__ unsigned f2tf32(float x) {
    unsigned r;
    asm("cvt.rna.tf32.f32 %0, %1;" : "=r"(r) : "f"(x));
    return r;
}

__device__ __forceinline__ void mma_tf32(
    float& c0, float& c1, float& c2, float& c3,
    unsigned a0, unsigned a1, unsigned a2, unsigned a3,
    unsigned b0, unsigned b1)
{
    asm volatile(
        "mma.sync.aligned.m16n8k8.row.col.f32.tf32.tf32.f32 "
        "{%0,%1,%2,%3}, {%4,%5,%6,%7}, {%8,%9}, {%0,%1,%2,%3};"
        : "+f"(c0), "+f"(c1), "+f"(c2), "+f"(c3)
        : "r"(a0), "r"(a1), "r"(a2), "r"(a3), "r"(b0), "r"(b1));
}

// ---------------------------------------------------------------------------
// 1x1-conv GEMM via 3xTF32 tensor-core split.
// out[o,n] = sum_c W[o,c] * X[c,n] + bias[o] (+ resid)
// Block tile 128(o=M) x 128(n=N), K-step 8, 256 threads = 8 warps laid out
// 4(M) x 2(N); warp tile 32x64 = 2 x 8 mma tiles of m16n8k8.
// Split: C += Ahi*Bhi + Alo*Bhi + Ahi*Blo  (error ~2^-22, well under 1e-3).
// smem row stride 136 words -> conflict-free fragment loads, aligned float4.
// ---------------------------------------------------------------------------
#define SMS 136

__device__ __forceinline__ void gemm_body_tc(
    const float* __restrict__ Xb,    // [C, N] for this batch
    const float* __restrict__ W,     // [C_out, C_in] row-major
    const float* __restrict__ bias,  // [C_out]
    float* __restrict__ outb,        // [C, N]
    const float* __restrict__ residb,// [C, N] or nullptr
    int obase, int nbase)
{
    __shared__ unsigned Ws[2][2][8][SMS];   // [buf][hi/lo][c][o]
    __shared__ unsigned Xs[2][2][8][SMS];   // [buf][hi/lo][c][n]

    const int tid  = threadIdx.x;
    const int lane = tid & 31;
    const int wrp  = tid >> 5;
    const int grp  = lane >> 2;     // 0..7
    const int qid  = lane & 3;      // 0..3
    const int warpM = wrp & 3;      // 0..3  (32 rows each)
    const int warpN = wrp >> 2;     // 0..1  (64 cols each)

    float c[2][8][4];
#pragma unroll
    for (int tm = 0; tm < 2; tm++)
#pragma unroll
        for (int tn = 0; tn < 8; tn++)
#pragma unroll
            for (int k = 0; k < 4; k++) c[tm][tn][k] = 0.0f;

    // loader mapping
    const int wo = tid >> 1;            // 0..127
    const int wc = (tid & 1) * 4;       // 0 or 4
    const int xc = tid >> 5;            // 0..7
    const int xn = (tid & 31) * 4;      // 0..124

    const float* wp = W + (obase + wo) * CDIM + wc;
    const float* xp = Xb + xc * NPIX + nbase + xn;

    // Preload k-step 0 into buffer 0
    {
        float4 wv = *(const float4*)(wp);
        float4 xv = *(const float4*)(xp);
        float wa[4] = {wv.x, wv.y, wv.z, wv.w};
#pragma unroll
        for (int j = 0; j < 4; j++) {
            unsigned h = f2tf32(wa[j]);
            Ws[0][0][wc + j][wo] = h;
            Ws[0][1][wc + j][wo] = __float_as_uint(wa[j] - __uint_as_float(h));
        }
        uint4 xh, xl;
        xh.x = f2tf32(xv.x); xl.x = __float_as_uint(xv.x - __uint_as_float(xh.x));
        xh.y = f2tf32(xv.y); xl.y = __float_as_uint(xv.y - __uint_as_float(xh.y));
        xh.z = f2tf32(xv.z); xl.z = __float_as_uint(xv.z - __uint_as_float(xh.z));
        xh.w = f2tf32(xv.w); xl.w = __float_as_uint(xv.w - __uint_as_float(xh.w));
        *(uint4*)&Xs[0][0][xc][xn] = xh;
        *(uint4*)&Xs[0][1][xc][xn] = xl;
    }
    __syncthreads();

    int buf = 0;
    for (int c0 = 8; c0 <= CDIM; c0 += 8) {
        const bool more = (c0 < CDIM);
        float4 wv, xv;
        if (more) {
            wv = *(const float4*)(wp + c0);
            xv = *(const float4*)(xp + (size_t)c0 * NPIX);
        }

        // ---- fragment loads from current buffer ----
        unsigned aH[2][4], aL[2][4], bH[8][2], bL[8][2];
#pragma unroll
        for (int tm = 0; tm < 2; tm++) {
            const int o = warpM * 32 + tm * 16 + grp;
            aH[tm][0] = Ws[buf][0][qid][o];
            aH[tm][1] = Ws[buf][0][qid][o + 8];
            aH[tm][2] = Ws[buf][0][qid + 4][o];
            aH[tm][3] = Ws[buf][0][qid + 4][o + 8];
            aL[tm][0] = Ws[buf][1][qid][o];
            aL[tm][1] = Ws[buf][1][qid][o + 8];
            aL[tm][2] = Ws[buf][1][qid + 4][o];
            aL[tm][3] = Ws[buf][1][qid + 4][o + 8];
        }
#pragma unroll
        for (int tn = 0; tn < 8; tn++) {
            const int n = warpN * 64 + tn * 8 + grp;
            bH[tn][0] = Xs[buf][0][qid][n];
            bH[tn][1] = Xs[buf][0][qid + 4][n];
            bL[tn][0] = Xs[buf][1][qid][n];
            bL[tn][1] = Xs[buf][1][qid + 4][n];
        }

        // ---- 16 tiles x 3 split mmas ----
#pragma unroll
        for (int tm = 0; tm < 2; tm++)
#pragma unroll
            for (int tn = 0; tn < 8; tn++) {
                mma_tf32(c[tm][tn][0], c[tm][tn][1], c[tm][tn][2], c[tm][tn][3],
                         aH[tm][0], aH[tm][1], aH[tm][2], aH[tm][3],
                         bH[tn][0], bH[tn][1]);
                mma_tf32(c[tm][tn][0], c[tm][tn][1], c[tm][tn][2], c[tm][tn][3],
                         aL[tm][0], aL[tm][1], aL[tm][2], aL[tm][3],
                         bH[tn][0], bH[tn][1]);
                mma_tf32(c[tm][tn][0], c[tm][tn][1], c[tm][tn][2], c[tm][tn][3],
                         aH[tm][0], aH[tm][1], aH[tm][2], aH[tm][3],
                         bL[tn][0], bL[tn][1]);
            }

        if (more) {
            const int nb = buf ^ 1;
            float wa[4] = {wv.x, wv.y, wv.z, wv.w};
#pragma unroll
            for (int j = 0; j < 4; j++) {
                unsigned h = f2tf32(wa[j]);
                Ws[nb][0][wc + j][wo] = h;
                Ws[nb][1][wc + j][wo] = __float_as_uint(wa[j] - __uint_as_float(h));
            }
            uint4 xh, xl;
            xh.x = f2tf32(xv.x); xl.x = __float_as_uint(xv.x - __uint_as_float(xh.x));
            xh.y = f2tf32(xv.y); xl.y = __float_as_uint(xv.y - __uint_as_float(xh.y));
            xh.z = f2tf32(xv.z); xl.z = __float_as_uint(xv.z - __uint_as_float(xh.z));
            xh.w = f2tf32(xv.w); xl.w = __float_as_uint(xv.w - __uint_as_float(xh.w));
            *(uint4*)&Xs[nb][0][xc][xn] = xh;
            *(uint4*)&Xs[nb][1][xc][xn] = xl;
            __syncthreads();
            buf = nb;
        }
    }

    // ---- epilogue: bias (+residual), float2 stores ----
#pragma unroll
    for (int tm = 0; tm < 2; tm++) {
        const int o0 = obase + warpM * 32 + tm * 16 + grp;
        const float bv0 = bias[o0];
        const float bv1 = bias[o0 + 8];
#pragma unroll
        for (int tn = 0; tn < 8; tn++) {
            const int n0 = nbase + warpN * 64 + tn * 8 + 2 * qid;
            float* p0 = outb + (size_t)o0 * NPIX + n0;
            float* p1 = outb + (size_t)(o0 + 8) * NPIX + n0;
            float2 v0, v1;
            v0.x = c[tm][tn][0] + bv0;
            v0.y = c[tm][tn][1] + bv0;
            v1.x = c[tm][tn][2] + bv1;
            v1.y = c[tm][tn][3] + bv1;
            if (residb != nullptr) {
                const float2 r0 = *(const float2*)(residb + (size_t)o0 * NPIX + n0);
                const float2 r1 = *(const float2*)(residb + (size_t)(o0 + 8) * NPIX + n0);
                v0.x += r0.x; v0.y += r0.y;
                v1.x += r1.x; v1.y += r1.y;
            }
            *(float2*)p0 = v0;
            *(float2*)p1 = v1;
        }
    }
}

// ---------------------------------------------------------------------------
// QKV projection: grid (N/128, C/128, 3*B). z selects {Q,K,V} x batch.
// ---------------------------------------------------------------------------
__global__ void __launch_bounds__(256, 1) qkv_kernel(
    const float* __restrict__ x,
    const float* __restrict__ Wq, const float* __restrict__ bq,
    const float* __restrict__ Wk, const float* __restrict__ bk,
    const float* __restrict__ Wv, const float* __restrict__ bv)
{
    const int z = blockIdx.z;
    const int mat = z >> 3;   // 0:Q 1:K 2:V
    const int b = z & 7;
    const float* W;
    const float* bias;
    float* out;
    if (mat == 0)      { W = Wq; bias = bq; out = g_Q; }
    else if (mat == 1) { W = Wk; bias = bk; out = g_K; }
    else               { W = Wv; bias = bv; out = g_V; }
    const size_t boff = (size_t)b * CDIM * NPIX;
    gemm_body_tc(x + boff, W, bias, out + boff, nullptr,
                 blockIdx.y * 128, blockIdx.x * 128);
}

// ---------------------------------------------------------------------------
// Output projection + residual: grid (N/128, C/128, B)
// ---------------------------------------------------------------------------
__global__ void __launch_bounds__(256, 1) oproj_kernel(
    const float* __restrict__ x,
    const float* __restrict__ Wo, const float* __restrict__ bo,
    float* __restrict__ out)
{
    const int b = blockIdx.z;
    const size_t boff = (size_t)b * CDIM * NPIX;
    gemm_body_tc(g_A + boff, Wo, bo, out + boff, x + boff,
                 blockIdx.y * 128, blockIdx.x * 128);
}

// ---------------------------------------------------------------------------
// Flash-style attention, one block per (b, h, 64-row i-tile). (unchanged,
// fp32 SIMT — proven correct at rel_err 2e-8; tensor-core port is next.)
// ---------------------------------------------------------------------------
#define VCOL(d, j) ((d) ^ ((j) & 0x3C))

__global__ void __launch_bounds__(256) attn_kernel()
{
    __shared__ float Qs[64 * 64];    // [d][i]
    __shared__ float KsPs[64 * 64];  // [d][j] then [i][j]
    __shared__ float Vt[64 * 64];    // [j][swizzled d]

    const int tid = threadIdx.x;
    const int tx = tid & 15;
    const int ty = tid >> 4;

    const int bh = blockIdx.y;
    const int b = bh >> 3;
    const int h = bh & 7;
    const int i0 = blockIdx.x * 64;

    const size_t base = ((size_t)b * CDIM + h * HDIM) * NPIX;
    const float* Qp = g_Q + base;
    const float* Kp = g_K + base;
    const float* Vp = g_V + base;
    float* Ap = g_A + base;

    // Load Q tile, pre-scaled by 1/sqrt(hd) = 0.125
    for (int t = tid; t < 1024; t += 256) {
        const int d = t >> 4;
        const int i4 = (t & 15) * 4;
        float4 q = *(const float4*)&Qp[(size_t)d * NPIX + i0 + i4];
        q.x *= 0.125f; q.y *= 0.125f; q.z *= 0.125f; q.w *= 0.125f;
        *(float4*)&Qs[d * 64 + i4] = q;
    }

    float rm[4], rl[4], o[4][4];
#pragma unroll
    for (int ii = 0; ii < 4; ii++) {
        rm[ii] = -1e30f;
        rl[ii] = 0.0f;
#pragma unroll
        for (int dd = 0; dd < 4; dd++) o[ii][dd] = 0.0f;
    }

    for (int j0 = 0; j0 < NPIX; j0 += 64) {
        __syncthreads();  // previous O-phase readers done (also fences Q load)

        // Load K tile ([d][j]) and V tile (transposed + swizzled [j][d])
        for (int t = tid; t < 1024; t += 256) {
            const int d = t >> 4;
            const int j4 = (t & 15) * 4;
            float4 kv = *(const float4*)&Kp[(size_t)d * NPIX + j0 + j4];
            *(float4*)&KsPs[d * 64 + j4] = kv;
            float4 vv = *(const float4*)&Vp[(size_t)d * NPIX + j0 + j4];
            Vt[(j4 + 0) * 64 + VCOL(d, j4 + 0)] = vv.x;
            Vt[(j4 + 1) * 64 + VCOL(d, j4 + 1)] = vv.y;
            Vt[(j4 + 2) * 64 + VCOL(d, j4 + 2)] = vv.z;
            Vt[(j4 + 3) * 64 + VCOL(d, j4 + 3)] = vv.w;
        }
        __syncthreads();

        // S = Q^T K (already scaled)
        float s[4][4];
#pragma unroll
        for (int ii = 0; ii < 4; ii++)
#pragma unroll
            for (int jj = 0; jj < 4; jj++) s[ii][jj] = 0.0f;

#pragma unroll 8
        for (int d = 0; d < 64; d++) {
            const float4 q = *(const float4*)&Qs[d * 64 + ty * 4];
            const float4 k = *(const float4*)&KsPs[d * 64 + tx * 4];
            s[0][0] += q.x * k.x; s[0][1] += q.x * k.y; s[0][2] += q.x * k.z; s[0][3] += q.x * k.w;
            s[1][0] += q.y * k.x; s[1][1] += q.y * k.y; s[1][2] += q.y * k.z; s[1][3] += q.y * k.w;
            s[2][0] += q.z * k.x; s[2][1] += q.z * k.y; s[2][2] += q.z * k.z; s[2][3] += q.z * k.w;
            s[3][0] += q.w * k.x; s[3][1] += q.w * k.y; s[3][2] += q.w * k.z; s[3][3] += q.w * k.w;
        }

        // Online softmax: rows i live in the 16 tx-lanes of a half-warp.
        float cval[4];
#pragma unroll
        for (int ii = 0; ii < 4; ii++) {
            float tm = fmaxf(fmaxf(s[ii][0], s[ii][1]), fmaxf(s[ii][2], s[ii][3]));
            tm = fmaxf(tm, __shfl_xor_sync(0xFFFFFFFFu, tm, 1));
            tm = fmaxf(tm, __shfl_xor_sync(0xFFFFFFFFu, tm, 2));
            tm = fmaxf(tm, __shfl_xor_sync(0xFFFFFFFFu, tm, 4));
            tm = fmaxf(tm, __shfl_xor_sync(0xFFFFFFFFu, tm, 8));
            const float mn = fmaxf(rm[ii], tm);
            const float cc = __expf(rm[ii] - mn);
            rm[ii] = mn;
            float ts = 0.0f;
#pragma unroll
            for (int jj = 0; jj < 4; jj++) {
                s[ii][jj] = __expf(s[ii][jj] - mn);
                ts += s[ii][jj];
            }
            ts += __shfl_xor_sync(0xFFFFFFFFu, ts, 1);
            ts += __shfl_xor_sync(0xFFFFFFFFu, ts, 2);
            ts += __shfl_xor_sync(0xFFFFFFFFu, ts, 4);
            ts += __shfl_xor_sync(0xFFFFFFFFu, ts, 8);
            rl[ii] = rl[ii] * cc + ts;
            cval[ii] = cc;
        }

        __syncthreads();  // all S-phase reads of Ks done before P overwrite

        // Write P[i][j] into the K-tile buffer (float4 along j).
#pragma unroll
        for (int ii = 0; ii < 4; ii++) {
            float4 p;
            p.x = s[ii][0]; p.y = s[ii][1]; p.z = s[ii][2]; p.w = s[ii][3];
            *(float4*)&KsPs[(ty * 4 + ii) * 64 + tx * 4] = p;
        }
        __syncthreads();

        // Rescale accumulators, then O += P * V^T
#pragma unroll
        for (int ii = 0; ii < 4; ii++) {
            const float cc = cval[ii];
#pragma unroll
            for (int dd = 0; dd < 4; dd++) o[ii][dd] *= cc;
        }

#pragma unroll 4
        for (int j = 0; j < 64; j++) {
            const float4 v = *(const float4*)&Vt[j * 64 + ((tx * 4) ^ (j & 0x3C))];
            const float p0 = KsPs[(ty * 4 + 0) * 64 + j];
            const float p1 = KsPs[(ty * 4 + 1) * 64 + j];
            const float p2 = KsPs[(ty * 4 + 2) * 64 + j];
            const float p3 = KsPs[(ty * 4 + 3) * 64 + j];
            o[0][0] += p0 * v.x; o[0][1] += p0 * v.y; o[0][2] += p0 * v.z; o[0][3] += p0 * v.w;
            o[1][0] += p1 * v.x; o[1][1] += p1 * v.y; o[1][2] += p1 * v.z; o[1][3] += p1 * v.w;
            o[2][0] += p2 * v.x; o[2][1] += p2 * v.y; o[2][2] += p2 * v.z; o[2][3] += p2 * v.w;
            o[3][0] += p3 * v.x; o[3][1] += p3 * v.y; o[3][2] += p3 * v.z; o[3][3] += p3 * v.w;
        }
    }

    // Normalize and stage O[d][i] in Qs (reuse), then coalesced global store.
    __syncthreads();
#pragma unroll
    for (int ii = 0; ii < 4; ii++) {
        const float inv = 1.0f / rl[ii];
#pragma unroll
        for (int dd = 0; dd < 4; dd++)
            Qs[(tx * 4 + dd) * 64 + ty * 4 + ii] = o[ii][dd] * inv;
    }
    __syncthreads();
    for (int t = tid; t < 1024; t += 256) {
        const int d = t >> 4;
        const int i4 = (t & 15) * 4;
        *(float4*)&Ap[(size_t)d * NPIX + i0 + i4] = *(const float4*)&Qs[d * 64 + i4];
    }
}

// ---------------------------------------------------------------------------
// Launch: QKV proj -> attention -> output proj (+residual).
// ---------------------------------------------------------------------------
extern "C" void kernel_launch(void* const* d_in, const int* in_sizes, int n_in,
                              void* d_out, int out_size)
{
    const float* x  = (const float*)d_in[0];
    const float* Wq = (const float*)d_in[1];
    const float* bq = (const float*)d_in[2];
    const float* Wk = (const float*)d_in[3];
    const float* bk = (const float*)d_in[4];
    const float* Wv = (const float*)d_in[5];
    const float* bv = (const float*)d_in[6];
    const float* Wo = (const float*)d_in[7];
    const float* bo = (const float*)d_in[8];
    float* out = (float*)d_out;

    qkv_kernel<<<dim3(NPIX / 128, CDIM / 128, 3 * BATCH), 256>>>(
        x, Wq, bq, Wk, bk, Wv, bv);
    attn_kernel<<<dim3(NPIX / 64, BATCH * NHEAD), 256>>>();
    oproj_kernel<<<dim3(NPIX / 128, CDIM / 128, BATCH), 256>>>(x, Wo, bo, out);
}

// round 4
// speedup vs baseline: 1.1653x; 1.0713x over previous
#include <cuda_runtime.h>

// Problem constants
#define BATCH 8
#define CDIM  512
#define NPIX  1024   // 32*32
#define NHEAD 8
#define HDIM  64

// ---------------------------------------------------------------------------
// Device-global scratch (no allocations allowed in kernel_launch).
// ---------------------------------------------------------------------------
__device__ float g_Q[BATCH * CDIM * NPIX];
__device__ float g_K[BATCH * CDIM * NPIX];
__device__ float g_V[BATCH * CDIM * NPIX];
__device__ float g_A[BATCH * CDIM * NPIX];

// ---------------------------------------------------------------------------
// TF32 helpers
// ---------------------------------------------------------------------------
__device__ __forceinline__ unsigned f2tf32(float x) {
    unsigned r;
    asm("cvt.rna.tf32.f32 %0, %1;" : "=r"(r) : "f"(x));
    return r;
}

__device__ __forceinline__ void mma_tf32(
    float& c0, float& c1, float& c2, float& c3,
    unsigned a0, unsigned a1, unsigned a2, unsigned a3,
    unsigned b0, unsigned b1)
{
    asm volatile(
        "mma.sync.aligned.m16n8k8.row.col.f32.tf32.tf32.f32 "
        "{%0,%1,%2,%3}, {%4,%5,%6,%7}, {%8,%9}, {%0,%1,%2,%3};"
        : "+f"(c0), "+f"(c1), "+f"(c2), "+f"(c3)
        : "r"(a0), "r"(a1), "r"(a2), "r"(a3), "r"(b0), "r"(b1));
}

// ---------------------------------------------------------------------------
// 1x1-conv GEMM via 3xTF32 tensor-core split. (unchanged from R3 — passed)
// ---------------------------------------------------------------------------
#define SMS 136

__device__ __forceinline__ void gemm_body_tc(
    const float* __restrict__ Xb,    // [C, N] for this batch
    const float* __restrict__ W,     // [C_out, C_in] row-major
    const float* __restrict__ bias,  // [C_out]
    float* __restrict__ outb,        // [C, N]
    const float* __restrict__ residb,// [C, N] or nullptr
    int obase, int nbase)
{
    __shared__ unsigned Ws[2][2][8][SMS];   // [buf][hi/lo][c][o]
    __shared__ unsigned Xs[2][2][8][SMS];   // [buf][hi/lo][c][n]

    const int tid  = threadIdx.x;
    const int lane = tid & 31;
    const int wrp  = tid >> 5;
    const int grp  = lane >> 2;     // 0..7
    const int qid  = lane & 3;      // 0..3
    const int warpM = wrp & 3;      // 0..3  (32 rows each)
    const int warpN = wrp >> 2;     // 0..1  (64 cols each)

    float c[2][8][4];
#pragma unroll
    for (int tm = 0; tm < 2; tm++)
#pragma unroll
        for (int tn = 0; tn < 8; tn++)
#pragma unroll
            for (int k = 0; k < 4; k++) c[tm][tn][k] = 0.0f;

    // loader mapping
    const int wo = tid >> 1;            // 0..127
    const int wc = (tid & 1) * 4;       // 0 or 4
    const int xc = tid >> 5;            // 0..7
    const int xn = (tid & 31) * 4;      // 0..124

    const float* wp = W + (obase + wo) * CDIM + wc;
    const float* xp = Xb + xc * NPIX + nbase + xn;

    // Preload k-step 0 into buffer 0
    {
        float4 wv = *(const float4*)(wp);
        float4 xv = *(const float4*)(xp);
        float wa[4] = {wv.x, wv.y, wv.z, wv.w};
#pragma unroll
        for (int j = 0; j < 4; j++) {
            unsigned h = f2tf32(wa[j]);
            Ws[0][0][wc + j][wo] = h;
            Ws[0][1][wc + j][wo] = __float_as_uint(wa[j] - __uint_as_float(h));
        }
        uint4 xh, xl;
        xh.x = f2tf32(xv.x); xl.x = __float_as_uint(xv.x - __uint_as_float(xh.x));
        xh.y = f2tf32(xv.y); xl.y = __float_as_uint(xv.y - __uint_as_float(xh.y));
        xh.z = f2tf32(xv.z); xl.z = __float_as_uint(xv.z - __uint_as_float(xh.z));
        xh.w = f2tf32(xv.w); xl.w = __float_as_uint(xv.w - __uint_as_float(xh.w));
        *(uint4*)&Xs[0][0][xc][xn] = xh;
        *(uint4*)&Xs[0][1][xc][xn] = xl;
    }
    __syncthreads();

    int buf = 0;
    for (int c0 = 8; c0 <= CDIM; c0 += 8) {
        const bool more = (c0 < CDIM);
        float4 wv, xv;
        if (more) {
            wv = *(const float4*)(wp + c0);
            xv = *(const float4*)(xp + (size_t)c0 * NPIX);
        }

        // ---- fragment loads from current buffer ----
        unsigned aH[2][4], aL[2][4], bH[8][2], bL[8][2];
#pragma unroll
        for (int tm = 0; tm < 2; tm++) {
            const int o = warpM * 32 + tm * 16 + grp;
            aH[tm][0] = Ws[buf][0][qid][o];
            aH[tm][1] = Ws[buf][0][qid][o + 8];
            aH[tm][2] = Ws[buf][0][qid + 4][o];
            aH[tm][3] = Ws[buf][0][qid + 4][o + 8];
            aL[tm][0] = Ws[buf][1][qid][o];
            aL[tm][1] = Ws[buf][1][qid][o + 8];
            aL[tm][2] = Ws[buf][1][qid + 4][o];
            aL[tm][3] = Ws[buf][1][qid + 4][o + 8];
        }
#pragma unroll
        for (int tn = 0; tn < 8; tn++) {
            const int n = warpN * 64 + tn * 8 + grp;
            bH[tn][0] = Xs[buf][0][qid][n];
            bH[tn][1] = Xs[buf][0][qid + 4][n];
            bL[tn][0] = Xs[buf][1][qid][n];
            bL[tn][1] = Xs[buf][1][qid + 4][n];
        }

        // ---- 16 tiles x 3 split mmas ----
#pragma unroll
        for (int tm = 0; tm < 2; tm++)
#pragma unroll
            for (int tn = 0; tn < 8; tn++) {
                mma_tf32(c[tm][tn][0], c[tm][tn][1], c[tm][tn][2], c[tm][tn][3],
                         aH[tm][0], aH[tm][1], aH[tm][2], aH[tm][3],
                         bH[tn][0], bH[tn][1]);
                mma_tf32(c[tm][tn][0], c[tm][tn][1], c[tm][tn][2], c[tm][tn][3],
                         aL[tm][0], aL[tm][1], aL[tm][2], aL[tm][3],
                         bH[tn][0], bH[tn][1]);
                mma_tf32(c[tm][tn][0], c[tm][tn][1], c[tm][tn][2], c[tm][tn][3],
                         aH[tm][0], aH[tm][1], aH[tm][2], aH[tm][3],
                         bL[tn][0], bL[tn][1]);
            }

        if (more) {
            const int nb = buf ^ 1;
            float wa[4] = {wv.x, wv.y, wv.z, wv.w};
#pragma unroll
            for (int j = 0; j < 4; j++) {
                unsigned h = f2tf32(wa[j]);
                Ws[nb][0][wc + j][wo] = h;
                Ws[nb][1][wc + j][wo] = __float_as_uint(wa[j] - __uint_as_float(h));
            }
            uint4 xh, xl;
            xh.x = f2tf32(xv.x); xl.x = __float_as_uint(xv.x - __uint_as_float(xh.x));
            xh.y = f2tf32(xv.y); xl.y = __float_as_uint(xv.y - __uint_as_float(xh.y));
            xh.z = f2tf32(xv.z); xl.z = __float_as_uint(xv.z - __uint_as_float(xh.z));
            xh.w = f2tf32(xv.w); xl.w = __float_as_uint(xv.w - __uint_as_float(xh.w));
            *(uint4*)&Xs[nb][0][xc][xn] = xh;
            *(uint4*)&Xs[nb][1][xc][xn] = xl;
            __syncthreads();
            buf = nb;
        }
    }

    // ---- epilogue: bias (+residual), float2 stores ----
#pragma unroll
    for (int tm = 0; tm < 2; tm++) {
        const int o0 = obase + warpM * 32 + tm * 16 + grp;
        const float bv0 = bias[o0];
        const float bv1 = bias[o0 + 8];
#pragma unroll
        for (int tn = 0; tn < 8; tn++) {
            const int n0 = nbase + warpN * 64 + tn * 8 + 2 * qid;
            float* p0 = outb + (size_t)o0 * NPIX + n0;
            float* p1 = outb + (size_t)(o0 + 8) * NPIX + n0;
            float2 v0, v1;
            v0.x = c[tm][tn][0] + bv0;
            v0.y = c[tm][tn][1] + bv0;
            v1.x = c[tm][tn][2] + bv1;
            v1.y = c[tm][tn][3] + bv1;
            if (residb != nullptr) {
                const float2 r0 = *(const float2*)(residb + (size_t)o0 * NPIX + n0);
                const float2 r1 = *(const float2*)(residb + (size_t)(o0 + 8) * NPIX + n0);
                v0.x += r0.x; v0.y += r0.y;
                v1.x += r1.x; v1.y += r1.y;
            }
            *(float2*)p0 = v0;
            *(float2*)p1 = v1;
        }
    }
}

// ---------------------------------------------------------------------------
// QKV projection: grid (N/128, C/128, 3*B). z selects {Q,K,V} x batch.
// ---------------------------------------------------------------------------
__global__ void __launch_bounds__(256, 1) qkv_kernel(
    const float* __restrict__ x,
    const float* __restrict__ Wq, const float* __restrict__ bq,
    const float* __restrict__ Wk, const float* __restrict__ bk,
    const float* __restrict__ Wv, const float* __restrict__ bv)
{
    const int z = blockIdx.z;
    const int mat = z >> 3;   // 0:Q 1:K 2:V
    const int b = z & 7;
    const float* W;
    const float* bias;
    float* out;
    if (mat == 0)      { W = Wq; bias = bq; out = g_Q; }
    else if (mat == 1) { W = Wk; bias = bk; out = g_K; }
    else               { W = Wv; bias = bv; out = g_V; }
    const size_t boff = (size_t)b * CDIM * NPIX;
    gemm_body_tc(x + boff, W, bias, out + boff, nullptr,
                 blockIdx.y * 128, blockIdx.x * 128);
}

// ---------------------------------------------------------------------------
// Output projection + residual: grid (N/128, C/128, B)
// ---------------------------------------------------------------------------
__global__ void __launch_bounds__(256, 1) oproj_kernel(
    const float* __restrict__ x,
    const float* __restrict__ Wo, const float* __restrict__ bo,
    float* __restrict__ out)
{
    const int b = blockIdx.z;
    const size_t boff = (size_t)b * CDIM * NPIX;
    gemm_body_tc(g_A + boff, Wo, bo, out + boff, x + boff,
                 blockIdx.y * 128, blockIdx.x * 128);
}

// ---------------------------------------------------------------------------
// Tensor-core flash attention. One block = (b, h, 128 i-rows), 8 warps;
// warp w owns i-rows [w*16, w*16+16) and the FULL 64-j tile -> softmax row
// reductions are warp-local (shfl over the 4 quad lanes).
//   S = (Q/8)^T K  via 3xTF32 split mma (Q frags in regs, K fp32 in smem,
//       hi/lo computed at fragment-load time)
//   online softmax in C-fragment registers
//   O += P V^T     via 3xTF32 split; the k-order permutation phi(k)=2k /
//       2(k-4)+1 makes the P C-fragment *be* the A-fragment (a={c0,c2,c1,c3}),
//       V b-frags read rows 8js+2q, 8js+2q+1. No transpose cost.
// Smem: Ks fp32 [64][72] (reads 8q+g: conflict-free), Vt fp32 [64][68]
// (reads 8q(+4)+g: conflict-free). Total 35.8 KB static.
// ---------------------------------------------------------------------------
__global__ void __launch_bounds__(256, 1) attn_kernel_tc()
{
    __shared__ float Ks[64 * 72];   // [d][j], row stride 72
    __shared__ float Vt[64 * 68];   // [j][d], row stride 68

    const int tid  = threadIdx.x;
    const int lane = tid & 31;
    const int wrp  = tid >> 5;      // 0..7
    const int g    = lane >> 2;     // 0..7
    const int q    = lane & 3;      // 0..3

    const int bh = blockIdx.y;
    const int b  = bh >> 3;
    const int h  = bh & 7;
    const int i0 = blockIdx.x * 128;
    const int iw = i0 + wrp * 16;

    const size_t base = ((size_t)b * CDIM + h * HDIM) * NPIX;
    const float* Qp = g_Q + base;
    const float* Kp = g_K + base;
    const float* Vp = g_V + base;
    float* Ap = g_A + base;

    // ---- Q fragments in registers (hi/lo), pre-scaled by 1/sqrt(64) ----
    unsigned qh[8][4], ql[8][4];
#pragma unroll
    for (int ks = 0; ks < 8; ks++) {
        const int d0 = ks * 8 + q;
        float v[4];
        v[0] = Qp[(size_t)d0 * NPIX + iw + g] * 0.125f;
        v[1] = Qp[(size_t)d0 * NPIX + iw + g + 8] * 0.125f;
        v[2] = Qp[(size_t)(d0 + 4) * NPIX + iw + g] * 0.125f;
        v[3] = Qp[(size_t)(d0 + 4) * NPIX + iw + g + 8] * 0.125f;
#pragma unroll
        for (int r = 0; r < 4; r++) {
            qh[ks][r] = f2tf32(v[r]);
            ql[ks][r] = __float_as_uint(v[r] - __uint_as_float(qh[ks][r]));
        }
    }

    float o[8][4];
#pragma unroll
    for (int dn = 0; dn < 8; dn++)
#pragma unroll
        for (int k = 0; k < 4; k++) o[dn][k] = 0.0f;
    float rmA = -1e30f, rmB = -1e30f, rlA = 0.0f, rlB = 0.0f;

#pragma unroll 1
    for (int j0 = 0; j0 < NPIX; j0 += 64) {
        __syncthreads();   // previous iteration's readers done

        // ---- load K tile [d][j] and V tile transposed [j][d] ----
        for (int t = tid; t < 1024; t += 256) {
            const int d  = t >> 4;
            const int j4 = (t & 15) * 4;
            float4 kv = *(const float4*)&Kp[(size_t)d * NPIX + j0 + j4];
            *(float4*)&Ks[d * 72 + j4] = kv;   // (72d + j4) % 4 == 0 -> aligned
            float4 vv = *(const float4*)&Vp[(size_t)d * NPIX + j0 + j4];
            Vt[(j4 + 0) * 68 + d] = vv.x;
            Vt[(j4 + 1) * 68 + d] = vv.y;
            Vt[(j4 + 2) * 68 + d] = vv.z;
            Vt[(j4 + 3) * 68 + d] = vv.w;
        }
        __syncthreads();

        // ---- S = Q^T K (3-term split) ----
        float s[8][4];
#pragma unroll
        for (int tn = 0; tn < 8; tn++)
#pragma unroll
            for (int k = 0; k < 4; k++) s[tn][k] = 0.0f;

#pragma unroll
        for (int ks = 0; ks < 8; ks++) {
            const int r0 = (ks * 8 + q) * 72;
            const int r1 = (ks * 8 + q + 4) * 72;
#pragma unroll
            for (int tn = 0; tn < 8; tn++) {
                const int jj = g + 8 * tn;
                const float k0 = Ks[r0 + jj];
                const float k1 = Ks[r1 + jj];
                const unsigned kh0 = f2tf32(k0);
                const unsigned kh1 = f2tf32(k1);
                const unsigned kl0 = __float_as_uint(k0 - __uint_as_float(kh0));
                const unsigned kl1 = __float_as_uint(k1 - __uint_as_float(kh1));
                mma_tf32(s[tn][0], s[tn][1], s[tn][2], s[tn][3],
                         qh[ks][0], qh[ks][1], qh[ks][2], qh[ks][3], kh0, kh1);
                mma_tf32(s[tn][0], s[tn][1], s[tn][2], s[tn][3],
                         ql[ks][0], ql[ks][1], ql[ks][2], ql[ks][3], kh0, kh1);
                mma_tf32(s[tn][0], s[tn][1], s[tn][2], s[tn][3],
                         qh[ks][0], qh[ks][1], qh[ks][2], qh[ks][3], kl0, kl1);
            }
        }

        // ---- online softmax: row g (c0,c1) and row g+8 (c2,c3) ----
        float mA = -1e30f, mB = -1e30f;
#pragma unroll
        for (int tn = 0; tn < 8; tn++) {
            mA = fmaxf(mA, fmaxf(s[tn][0], s[tn][1]));
            mB = fmaxf(mB, fmaxf(s[tn][2], s[tn][3]));
        }
        mA = fmaxf(mA, __shfl_xor_sync(0xFFFFFFFFu, mA, 1));
        mA = fmaxf(mA, __shfl_xor_sync(0xFFFFFFFFu, mA, 2));
        mB = fmaxf(mB, __shfl_xor_sync(0xFFFFFFFFu, mB, 1));
        mB = fmaxf(mB, __shfl_xor_sync(0xFFFFFFFFu, mB, 2));

        const float mnA = fmaxf(rmA, mA);
        const float mnB = fmaxf(rmB, mB);
        const float ccA = __expf(rmA - mnA);
        const float ccB = __expf(rmB - mnB);
        rmA = mnA; rmB = mnB;

        float tsA = 0.0f, tsB = 0.0f;
#pragma unroll
        for (int tn = 0; tn < 8; tn++) {
            s[tn][0] = __expf(s[tn][0] - mnA);
            s[tn][1] = __expf(s[tn][1] - mnA);
            s[tn][2] = __expf(s[tn][2] - mnB);
            s[tn][3] = __expf(s[tn][3] - mnB);
            tsA += s[tn][0] + s[tn][1];
            tsB += s[tn][2] + s[tn][3];
        }
        tsA += __shfl_xor_sync(0xFFFFFFFFu, tsA, 1);
        tsA += __shfl_xor_sync(0xFFFFFFFFu, tsA, 2);
        tsB += __shfl_xor_sync(0xFFFFFFFFu, tsB, 1);
        tsB += __shfl_xor_sync(0xFFFFFFFFu, tsB, 2);
        rlA = rlA * ccA + tsA;
        rlB = rlB * ccB + tsB;

#pragma unroll
        for (int dn = 0; dn < 8; dn++) {
            o[dn][0] *= ccA; o[dn][1] *= ccA;
            o[dn][2] *= ccB; o[dn][3] *= ccB;
        }

        // ---- O += P V^T (3-term split, k-order phi: a = {c0,c2,c1,c3}) ----
#pragma unroll
        for (int js = 0; js < 8; js++) {
            unsigned ph[4], pl[4];
            const float a0 = s[js][0], a1 = s[js][2], a2 = s[js][1], a3 = s[js][3];
            ph[0] = f2tf32(a0); pl[0] = __float_as_uint(a0 - __uint_as_float(ph[0]));
            ph[1] = f2tf32(a1); pl[1] = __float_as_uint(a1 - __uint_as_float(ph[1]));
            ph[2] = f2tf32(a2); pl[2] = __float_as_uint(a2 - __uint_as_float(ph[2]));
            ph[3] = f2tf32(a3); pl[3] = __float_as_uint(a3 - __uint_as_float(ph[3]));
            const int rv0 = (js * 8 + 2 * q) * 68;
            const int rv1 = (js * 8 + 2 * q + 1) * 68;
#pragma unroll
            for (int dn = 0; dn < 8; dn++) {
                const int dd = g + 8 * dn;
                const float v0 = Vt[rv0 + dd];
                const float v1 = Vt[rv1 + dd];
                const unsigned vh0 = f2tf32(v0);
                const unsigned vh1 = f2tf32(v1);
                const unsigned vl0 = __float_as_uint(v0 - __uint_as_float(vh0));
                const unsigned vl1 = __float_as_uint(v1 - __uint_as_float(vh1));
                mma_tf32(o[dn][0], o[dn][1], o[dn][2], o[dn][3],
                         ph[0], ph[1], ph[2], ph[3], vh0, vh1);
                mma_tf32(o[dn][0], o[dn][1], o[dn][2], o[dn][3],
                         pl[0], pl[1], pl[2], pl[3], vh0, vh1);
                mma_tf32(o[dn][0], o[dn][1], o[dn][2], o[dn][3],
                         ph[0], ph[1], ph[2], ph[3], vl0, vl1);
            }
        }
    }

    // ---- normalize + store O[i][d] into g_A[d][i] ----
    const float iA = 1.0f / rlA;
    const float iB = 1.0f / rlB;
#pragma unroll
    for (int dn = 0; dn < 8; dn++) {
        const int d0 = dn * 8 + 2 * q;
        Ap[(size_t)d0 * NPIX + iw + g]           = o[dn][0] * iA;
        Ap[(size_t)(d0 + 1) * NPIX + iw + g]     = o[dn][1] * iA;
        Ap[(size_t)d0 * NPIX + iw + g + 8]       = o[dn][2] * iB;
        Ap[(size_t)(d0 + 1) * NPIX + iw + g + 8] = o[dn][3] * iB;
    }
}

// ---------------------------------------------------------------------------
// Launch: QKV proj -> attention -> output proj (+residual).
// ---------------------------------------------------------------------------
extern "C" void kernel_launch(void* const* d_in, const int* in_sizes, int n_in,
                              void* d_out, int out_size)
{
    const float* x  = (const float*)d_in[0];
    const float* Wq = (const float*)d_in[1];
    const float* bq = (const float*)d_in[2];
    const float* Wk = (const float*)d_in[3];
    const float* bk = (const float*)d_in[4];
    const float* Wv = (const float*)d_in[5];
    const float* bv = (const float*)d_in[6];
    const float* Wo = (const float*)d_in[7];
    const float* bo = (const float*)d_in[8];
    float* out = (float*)d_out;

    qkv_kernel<<<dim3(NPIX / 128, CDIM / 128, 3 * BATCH), 256>>>(
        x, Wq, bq, Wk, bk, Wv, bv);
    attn_kernel_tc<<<dim3(NPIX / 128, BATCH * NHEAD), 256>>>();
    oproj_kernel<<<dim3(NPIX / 128, CDIM / 128, BATCH), 256>>>(x, Wo, bo, out);
}

// round 5
// speedup vs baseline: 2.7620x; 2.3703x over previous
#include <cuda_runtime.h>

// Problem constants
#define BATCH 8
#define CDIM  512
#define NPIX  1024   // 32*32
#define NHEAD 8
#define HDIM  64

// ---------------------------------------------------------------------------
// Device-global scratch (no allocations allowed in kernel_launch).
// ---------------------------------------------------------------------------
__device__ float g_Q[BATCH * CDIM * NPIX];
__device__ float g_K[BATCH * CDIM * NPIX];
__device__ float g_V[BATCH * CDIM * NPIX];
__device__ float g_A[BATCH * CDIM * NPIX];

// ---------------------------------------------------------------------------
// TF32 helpers
// ---------------------------------------------------------------------------
__device__ __forceinline__ unsigned f2tf32(float x) {
    unsigned r;
    asm("cvt.rna.tf32.f32 %0, %1;" : "=r"(r) : "f"(x));
    return r;
}

__device__ __forceinline__ void mma_tf32(
    float& c0, float& c1, float& c2, float& c3,
    unsigned a0, unsigned a1, unsigned a2, unsigned a3,
    unsigned b0, unsigned b1)
{
    asm volatile(
        "mma.sync.aligned.m16n8k8.row.col.f32.tf32.tf32.f32 "
        "{%0,%1,%2,%3}, {%4,%5,%6,%7}, {%8,%9}, {%0,%1,%2,%3};"
        : "+f"(c0), "+f"(c1), "+f"(c2), "+f"(c3)
        : "r"(a0), "r"(a1), "r"(a2), "r"(a3), "r"(b0), "r"(b1));
}

// ---------------------------------------------------------------------------
// 1x1-conv GEMM via single-TF32 tensor-core mma.
// out[o,n] = sum_c W[o,c] * X[c,n] + bias[o] (+ resid)
// Block 128(M) x 128(N), K-step 8, 8 warps 4x2, warp tile 32x64 = 16 mma.
// Operands converted to tf32 ONCE at smem-store time (single plane each).
// Error ~2^-11 per operand -> final rel_err ~1e-5 after residual dilution.
// ---------------------------------------------------------------------------
#define SMS 136

__device__ __forceinline__ void gemm_body_tc(
    const float* __restrict__ Xb,    // [C, N] for this batch
    const float* __restrict__ W,     // [C_out, C_in] row-major
    const float* __restrict__ bias,  // [C_out]
    float* __restrict__ outb,        // [C, N]
    const float* __restrict__ residb,// [C, N] or nullptr
    int obase, int nbase)
{
    __shared__ unsigned Ws[2][8][SMS];   // [buf][c][o] tf32 bits
    __shared__ unsigned Xs[2][8][SMS];   // [buf][c][n] tf32 bits

    const int tid  = threadIdx.x;
    const int lane = tid & 31;
    const int wrp  = tid >> 5;
    const int grp  = lane >> 2;     // 0..7
    const int qid  = lane & 3;      // 0..3
    const int warpM = wrp & 3;      // 0..3  (32 rows each)
    const int warpN = wrp >> 2;     // 0..1  (64 cols each)

    float c[2][8][4];
#pragma unroll
    for (int tm = 0; tm < 2; tm++)
#pragma unroll
        for (int tn = 0; tn < 8; tn++)
#pragma unroll
            for (int k = 0; k < 4; k++) c[tm][tn][k] = 0.0f;

    // loader mapping
    const int wo = tid >> 1;            // 0..127
    const int wc = (tid & 1) * 4;       // 0 or 4
    const int xc = tid >> 5;            // 0..7
    const int xn = (tid & 31) * 4;      // 0..124

    const float* wp = W + (obase + wo) * CDIM + wc;
    const float* xp = Xb + xc * NPIX + nbase + xn;

    // Preload k-step 0 into buffer 0
    {
        float4 wv = *(const float4*)(wp);
        float4 xv = *(const float4*)(xp);
        Ws[0][wc + 0][wo] = f2tf32(wv.x);
        Ws[0][wc + 1][wo] = f2tf32(wv.y);
        Ws[0][wc + 2][wo] = f2tf32(wv.z);
        Ws[0][wc + 3][wo] = f2tf32(wv.w);
        uint4 xh;
        xh.x = f2tf32(xv.x); xh.y = f2tf32(xv.y);
        xh.z = f2tf32(xv.z); xh.w = f2tf32(xv.w);
        *(uint4*)&Xs[0][xc][xn] = xh;
    }
    __syncthreads();

    int buf = 0;
    for (int c0 = 8; c0 <= CDIM; c0 += 8) {
        const bool more = (c0 < CDIM);
        float4 wv, xv;
        if (more) {
            wv = *(const float4*)(wp + c0);
            xv = *(const float4*)(xp + (size_t)c0 * NPIX);
        }

        // ---- fragment loads from current buffer ----
        unsigned aH[2][4], bH[8][2];
#pragma unroll
        for (int tm = 0; tm < 2; tm++) {
            const int o = warpM * 32 + tm * 16 + grp;
            aH[tm][0] = Ws[buf][qid][o];
            aH[tm][1] = Ws[buf][qid][o + 8];
            aH[tm][2] = Ws[buf][qid + 4][o];
            aH[tm][3] = Ws[buf][qid + 4][o + 8];
        }
#pragma unroll
        for (int tn = 0; tn < 8; tn++) {
            const int n = warpN * 64 + tn * 8 + grp;
            bH[tn][0] = Xs[buf][qid][n];
            bH[tn][1] = Xs[buf][qid + 4][n];
        }

        // ---- 16 mma tiles ----
#pragma unroll
        for (int tm = 0; tm < 2; tm++)
#pragma unroll
            for (int tn = 0; tn < 8; tn++)
                mma_tf32(c[tm][tn][0], c[tm][tn][1], c[tm][tn][2], c[tm][tn][3],
                         aH[tm][0], aH[tm][1], aH[tm][2], aH[tm][3],
                         bH[tn][0], bH[tn][1]);

        if (more) {
            const int nb = buf ^ 1;
            Ws[nb][wc + 0][wo] = f2tf32(wv.x);
            Ws[nb][wc + 1][wo] = f2tf32(wv.y);
            Ws[nb][wc + 2][wo] = f2tf32(wv.z);
            Ws[nb][wc + 3][wo] = f2tf32(wv.w);
            uint4 xh;
            xh.x = f2tf32(xv.x); xh.y = f2tf32(xv.y);
            xh.z = f2tf32(xv.z); xh.w = f2tf32(xv.w);
            *(uint4*)&Xs[nb][xc][xn] = xh;
            __syncthreads();
            buf = nb;
        }
    }

    // ---- epilogue: bias (+residual), float2 stores ----
#pragma unroll
    for (int tm = 0; tm < 2; tm++) {
        const int o0 = obase + warpM * 32 + tm * 16 + grp;
        const float bv0 = bias[o0];
        const float bv1 = bias[o0 + 8];
#pragma unroll
        for (int tn = 0; tn < 8; tn++) {
            const int n0 = nbase + warpN * 64 + tn * 8 + 2 * qid;
            float* p0 = outb + (size_t)o0 * NPIX + n0;
            float* p1 = outb + (size_t)(o0 + 8) * NPIX + n0;
            float2 v0, v1;
            v0.x = c[tm][tn][0] + bv0;
            v0.y = c[tm][tn][1] + bv0;
            v1.x = c[tm][tn][2] + bv1;
            v1.y = c[tm][tn][3] + bv1;
            if (residb != nullptr) {
                const float2 r0 = *(const float2*)(residb + (size_t)o0 * NPIX + n0);
                const float2 r1 = *(const float2*)(residb + (size_t)(o0 + 8) * NPIX + n0);
                v0.x += r0.x; v0.y += r0.y;
                v1.x += r1.x; v1.y += r1.y;
            }
            *(float2*)p0 = v0;
            *(float2*)p1 = v1;
        }
    }
}

// ---------------------------------------------------------------------------
// QKV projection: grid (N/128, C/128, 3*B). z selects {Q,K,V} x batch.
// ---------------------------------------------------------------------------
__global__ void __launch_bounds__(256, 2) qkv_kernel(
    const float* __restrict__ x,
    const float* __restrict__ Wq, const float* __restrict__ bq,
    const float* __restrict__ Wk, const float* __restrict__ bk,
    const float* __restrict__ Wv, const float* __restrict__ bv)
{
    const int z = blockIdx.z;
    const int mat = z >> 3;   // 0:Q 1:K 2:V
    const int b = z & 7;
    const float* W;
    const float* bias;
    float* out;
    if (mat == 0)      { W = Wq; bias = bq; out = g_Q; }
    else if (mat == 1) { W = Wk; bias = bk; out = g_K; }
    else               { W = Wv; bias = bv; out = g_V; }
    const size_t boff = (size_t)b * CDIM * NPIX;
    gemm_body_tc(x + boff, W, bias, out + boff, nullptr,
                 blockIdx.y * 128, blockIdx.x * 128);
}

// ---------------------------------------------------------------------------
// Output projection + residual: grid (N/128, C/128, B)
// ---------------------------------------------------------------------------
__global__ void __launch_bounds__(256, 2) oproj_kernel(
    const float* __restrict__ x,
    const float* __restrict__ Wo, const float* __restrict__ bo,
    float* __restrict__ out)
{
    const int b = blockIdx.z;
    const size_t boff = (size_t)b * CDIM * NPIX;
    gemm_body_tc(g_A + boff, Wo, bo, out + boff, x + boff,
                 blockIdx.y * 128, blockIdx.x * 128);
}

// ---------------------------------------------------------------------------
// Tensor-core flash attention, single-TF32. One block = (b,h,128 i-rows),
// 8 warps; warp w owns i-rows [w*16,w*16+16) x full 64-j tile.
// K and V tiles are converted to tf32 ONCE in the cooperative load phase and
// stored pre-rounded in smem (shared by all warps; kills the R4 redundant
// per-warp hi/lo conversion that dominated runtime).
//   S = (Q/8)^T K  (Q frags tf32 in regs, K tf32 in smem)
//   online softmax in C-fragment registers
//   O += P V^T     (phi k-permutation: P C-frag == A-frag, a={c0,c2,c1,c3})
// Smem: Ks [64][72] (reads 8q+g conflict-free), Vt [64][68] (8q(+4)+g
// conflict-free). 35.8 KB static; __launch_bounds__(256,2) -> 2 CTAs/SM.
// ---------------------------------------------------------------------------
__global__ void __launch_bounds__(256, 2) attn_kernel_tc()
{
    __shared__ unsigned Ks[64 * 72];   // [d][j] tf32 bits, row stride 72
    __shared__ unsigned Vt[64 * 68];   // [j][d] tf32 bits, row stride 68

    const int tid  = threadIdx.x;
    const int lane = tid & 31;
    const int wrp  = tid >> 5;      // 0..7
    const int g    = lane >> 2;     // 0..7
    const int q    = lane & 3;      // 0..3

    const int bh = blockIdx.y;
    const int b  = bh >> 3;
    const int h  = bh & 7;
    const int i0 = blockIdx.x * 128;
    const int iw = i0 + wrp * 16;

    const size_t base = ((size_t)b * CDIM + h * HDIM) * NPIX;
    const float* Qp = g_Q + base;
    const float* Kp = g_K + base;
    const float* Vp = g_V + base;
    float* Ap = g_A + base;

    // ---- Q fragments in registers (tf32), pre-scaled by 1/sqrt(64) ----
    unsigned qh[8][4];
#pragma unroll
    for (int ks = 0; ks < 8; ks++) {
        const int d0 = ks * 8 + q;
        qh[ks][0] = f2tf32(Qp[(size_t)d0 * NPIX + iw + g] * 0.125f);
        qh[ks][1] = f2tf32(Qp[(size_t)d0 * NPIX + iw + g + 8] * 0.125f);
        qh[ks][2] = f2tf32(Qp[(size_t)(d0 + 4) * NPIX + iw + g] * 0.125f);
        qh[ks][3] = f2tf32(Qp[(size_t)(d0 + 4) * NPIX + iw + g + 8] * 0.125f);
    }

    float o[8][4];
#pragma unroll
    for (int dn = 0; dn < 8; dn++)
#pragma unroll
        for (int k = 0; k < 4; k++) o[dn][k] = 0.0f;
    float rmA = -1e30f, rmB = -1e30f, rlA = 0.0f, rlB = 0.0f;

#pragma unroll 1
    for (int j0 = 0; j0 < NPIX; j0 += 64) {
        __syncthreads();   // previous iteration's readers done

        // ---- load + convert K tile [d][j] and V tile transposed [j][d] ----
        for (int t = tid; t < 1024; t += 256) {
            const int d  = t >> 4;
            const int j4 = (t & 15) * 4;
            float4 kv = *(const float4*)&Kp[(size_t)d * NPIX + j0 + j4];
            uint4 kh;
            kh.x = f2tf32(kv.x); kh.y = f2tf32(kv.y);
            kh.z = f2tf32(kv.z); kh.w = f2tf32(kv.w);
            *(uint4*)&Ks[d * 72 + j4] = kh;    // (72d + j4) % 4 == 0 -> aligned
            float4 vv = *(const float4*)&Vp[(size_t)d * NPIX + j0 + j4];
            Vt[(j4 + 0) * 68 + d] = f2tf32(vv.x);
            Vt[(j4 + 1) * 68 + d] = f2tf32(vv.y);
            Vt[(j4 + 2) * 68 + d] = f2tf32(vv.z);
            Vt[(j4 + 3) * 68 + d] = f2tf32(vv.w);
        }
        __syncthreads();

        // ---- S = Q^T K ----
        float s[8][4];
#pragma unroll
        for (int tn = 0; tn < 8; tn++)
#pragma unroll
            for (int k = 0; k < 4; k++) s[tn][k] = 0.0f;

#pragma unroll
        for (int ks = 0; ks < 8; ks++) {
            const int r0 = (ks * 8 + q) * 72;
            const int r1 = (ks * 8 + q + 4) * 72;
#pragma unroll
            for (int tn = 0; tn < 8; tn++) {
                const int jj = g + 8 * tn;
                mma_tf32(s[tn][0], s[tn][1], s[tn][2], s[tn][3],
                         qh[ks][0], qh[ks][1], qh[ks][2], qh[ks][3],
                         Ks[r0 + jj], Ks[r1 + jj]);
            }
        }

        // ---- online softmax: row g (c0,c1) and row g+8 (c2,c3) ----
        float mA = -1e30f, mB = -1e30f;
#pragma unroll
        for (int tn = 0; tn < 8; tn++) {
            mA = fmaxf(mA, fmaxf(s[tn][0], s[tn][1]));
            mB = fmaxf(mB, fmaxf(s[tn][2], s[tn][3]));
        }
        mA = fmaxf(mA, __shfl_xor_sync(0xFFFFFFFFu, mA, 1));
        mA = fmaxf(mA, __shfl_xor_sync(0xFFFFFFFFu, mA, 2));
        mB = fmaxf(mB, __shfl_xor_sync(0xFFFFFFFFu, mB, 1));
        mB = fmaxf(mB, __shfl_xor_sync(0xFFFFFFFFu, mB, 2));

        const float mnA = fmaxf(rmA, mA);
        const float mnB = fmaxf(rmB, mB);
        const float ccA = __expf(rmA - mnA);
        const float ccB = __expf(rmB - mnB);
        rmA = mnA; rmB = mnB;

        float tsA = 0.0f, tsB = 0.0f;
#pragma unroll
        for (int tn = 0; tn < 8; tn++) {
            s[tn][0] = __expf(s[tn][0] - mnA);
            s[tn][1] = __expf(s[tn][1] - mnA);
            s[tn][2] = __expf(s[tn][2] - mnB);
            s[tn][3] = __expf(s[tn][3] - mnB);
            tsA += s[tn][0] + s[tn][1];
            tsB += s[tn][2] + s[tn][3];
        }
        tsA += __shfl_xor_sync(0xFFFFFFFFu, tsA, 1);
        tsA += __shfl_xor_sync(0xFFFFFFFFu, tsA, 2);
        tsB += __shfl_xor_sync(0xFFFFFFFFu, tsB, 1);
        tsB += __shfl_xor_sync(0xFFFFFFFFu, tsB, 2);
        rlA = rlA * ccA + tsA;
        rlB = rlB * ccB + tsB;

#pragma unroll
        for (int dn = 0; dn < 8; dn++) {
            o[dn][0] *= ccA; o[dn][1] *= ccA;
            o[dn][2] *= ccB; o[dn][3] *= ccB;
        }

        // ---- O += P V^T (k-order phi: a = {c0,c2,c1,c3}) ----
#pragma unroll
        for (int js = 0; js < 8; js++) {
            unsigned ph[4];
            ph[0] = f2tf32(s[js][0]);
            ph[1] = f2tf32(s[js][2]);
            ph[2] = f2tf32(s[js][1]);
            ph[3] = f2tf32(s[js][3]);
            const int rv0 = (js * 8 + 2 * q) * 68;
            const int rv1 = (js * 8 + 2 * q + 1) * 68;
#pragma unroll
            for (int dn = 0; dn < 8; dn++) {
                const int dd = g + 8 * dn;
                mma_tf32(o[dn][0], o[dn][1], o[dn][2], o[dn][3],
                         ph[0], ph[1], ph[2], ph[3],
                         Vt[rv0 + dd], Vt[rv1 + dd]);
            }
        }
    }

    // ---- normalize + store O[i][d] into g_A[d][i] ----
    const float iA = 1.0f / rlA;
    const float iB = 1.0f / rlB;
#pragma unroll
    for (int dn = 0; dn < 8; dn++) {
        const int d0 = dn * 8 + 2 * q;
        Ap[(size_t)d0 * NPIX + iw + g]           = o[dn][0] * iA;
        Ap[(size_t)(d0 + 1) * NPIX + iw + g]     = o[dn][1] * iA;
        Ap[(size_t)d0 * NPIX + iw + g + 8]       = o[dn][2] * iB;
        Ap[(size_t)(d0 + 1) * NPIX + iw + g + 8] = o[dn][3] * iB;
    }
}

// ---------------------------------------------------------------------------
// Launch: QKV proj -> attention -> output proj (+residual).
// ---------------------------------------------------------------------------
extern "C" void kernel_launch(void* const* d_in, const int* in_sizes, int n_in,
                              void* d_out, int out_size)
{
    const float* x  = (const float*)d_in[0];
    const float* Wq = (const float*)d_in[1];
    const float* bq = (const float*)d_in[2];
    const float* Wk = (const float*)d_in[3];
    const float* bk = (const float*)d_in[4];
    const float* Wv = (const float*)d_in[5];
    const float* bv = (const float*)d_in[6];
    const float* Wo = (const float*)d_in[7];
    const float* bo = (const float*)d_in[8];
    float* out = (float*)d_out;

    qkv_kernel<<<dim3(NPIX / 128, CDIM / 128, 3 * BATCH), 256>>>(
        x, Wq, bq, Wk, bk, Wv, bv);
    attn_kernel_tc<<<dim3(NPIX / 128, BATCH * NHEAD), 256>>>();
    oproj_kernel<<<dim3(NPIX / 128, CDIM / 128, BATCH), 256>>>(x, Wo, bo, out);
}